// round 15
// baseline (speedup 1.0000x reference)
#include <cuda_runtime.h>
#include <cuda_bf16.h>
#include <math.h>

// Problem constants
#define HEADS 16
#define DMODEL 1024
#define KDIM 64
#define MFF 4096
#define MEMLEN 3
#define SEQ 512
#define BATCH 4
#define NROWS (SEQ * BATCH)            // 2048
#define LTOT ((MEMLEN + 1) * SEQ)      // 2048
#define KVROWS (LTOT * BATCH)          // 8192
#define HKD (HEADS * KDIM * DMODEL)    // 1048576 elems per qkv/c weight

// ---------------- scratch (no allocation allowed) ----------------
__device__ float g_upre[NROWS * DMODEL];
__device__ float g_u[NROWS * DMODEL];
__device__ __nv_bfloat16 g_wh[12 * 1024 * 1024];
__device__ __nv_bfloat16 g_wl[12 * 1024 * 1024];
__device__ __nv_bfloat16 g_xmh[KVROWS * DMODEL];
__device__ __nv_bfloat16 g_xml[KVROWS * DMODEL];
__device__ __nv_bfloat16 g_qh[NROWS * DMODEL];
__device__ __nv_bfloat16 g_ql[NROWS * DMODEL];
__device__ __nv_bfloat16 g_kh[KVROWS * DMODEL];
__device__ __nv_bfloat16 g_kl[KVROWS * DMODEL];
__device__ __nv_bfloat16 g_vh[KVROWS * DMODEL];
__device__ __nv_bfloat16 g_vl[KVROWS * DMODEL];
__device__ __nv_bfloat16 g_avh[NROWS * DMODEL];
__device__ __nv_bfloat16 g_avl[NROWS * DMODEL];
__device__ __nv_bfloat16 g_uh[NROWS * DMODEL];
__device__ __nv_bfloat16 g_ul[NROWS * DMODEL];
__device__ __nv_bfloat16 g_ffh[NROWS * MFF];
__device__ __nv_bfloat16 g_ffl[NROWS * MFF];

#define WQ_OFF 0
#define WK_OFF (1 * HKD)
#define WV_OFF (2 * HKD)
#define WC_OFF (3 * HKD)
#define W1_OFF (4 * HKD)
#define W2_OFF (8 * HKD)

// ---------------- helpers ----------------
__device__ __forceinline__ unsigned smem_u32(const void* p) {
    return (unsigned)__cvta_generic_to_shared(p);
}
__device__ __forceinline__ void cp_async16(unsigned dst, const void* src) {
    asm volatile("cp.async.cg.shared.global [%0], [%1], 16;" :: "r"(dst), "l"(src));
}
__device__ __forceinline__ void cp_commit() {
    asm volatile("cp.async.commit_group;");
}
__device__ __forceinline__ void cp_wait0() {
    asm volatile("cp.async.wait_group 0;");
}
__device__ __forceinline__ void ldm_x4(unsigned* r, unsigned addr) {
    asm volatile("ldmatrix.sync.aligned.m8n8.x4.shared.b16 {%0,%1,%2,%3}, [%4];"
                 : "=r"(r[0]), "=r"(r[1]), "=r"(r[2]), "=r"(r[3]) : "r"(addr));
}
__device__ __forceinline__ void ldm_x4_t(unsigned* r, unsigned addr) {
    asm volatile("ldmatrix.sync.aligned.m8n8.x4.trans.shared.b16 {%0,%1,%2,%3}, [%4];"
                 : "=r"(r[0]), "=r"(r[1]), "=r"(r[2]), "=r"(r[3]) : "r"(addr));
}
__device__ __forceinline__ void mma_bf16(float* d, const unsigned* a,
                                         unsigned b0, unsigned b1) {
    asm volatile("mma.sync.aligned.m16n8k16.row.col.f32.bf16.bf16.f32 "
                 "{%0,%1,%2,%3}, {%4,%5,%6,%7}, {%8,%9}, {%0,%1,%2,%3};"
                 : "+f"(d[0]), "+f"(d[1]), "+f"(d[2]), "+f"(d[3])
                 : "r"(a[0]), "r"(a[1]), "r"(a[2]), "r"(a[3]), "r"(b0), "r"(b1));
}
__device__ __forceinline__ __nv_bfloat162 split_hi2(float x, float y) {
    return __nv_bfloat162(__float2bfloat16_rn(x), __float2bfloat16_rn(y));
}
__device__ __forceinline__ __nv_bfloat162 split_lo2(float x, float y,
                                                    __nv_bfloat162 h) {
    return __nv_bfloat162(
        __float2bfloat16_rn(x - __bfloat162float(h.x)),
        __float2bfloat16_rn(y - __bfloat162float(h.y)));
}
__device__ __forceinline__ unsigned pack_hi2(float a, float b) {
    __nv_bfloat162 t = split_hi2(a, b);
    return reinterpret_cast<unsigned&>(t);
}
__device__ __forceinline__ unsigned pack_lo2(float a, float b, unsigned hibits) {
    __nv_bfloat162 h = reinterpret_cast<__nv_bfloat162&>(hibits);
    __nv_bfloat162 t = split_lo2(a, b, h);
    return reinterpret_cast<unsigned&>(t);
}

// ---------------- fused fp32 -> (hi,lo) bf16 split, ALL regions in one launch ----
#define SC1 262144
#define SC2 524288
#define SC3 786432
#define SC4 1048576
#define SC5 2097152
#define SC6 3145728
#define SC7 4718592
#define SC8 5242880   // total chunks; grid = SC8/256 = 20480

__global__ __launch_bounds__(256) void fused_split_kernel(
    const float* __restrict__ wq, const float* __restrict__ wk,
    const float* __restrict__ wv, const float* __restrict__ wc,
    const float* __restrict__ w1, const float* __restrict__ w2,
    const float* __restrict__ memory, const float* __restrict__ x,
    __nv_bfloat16* __restrict__ wh, __nv_bfloat16* __restrict__ wl,
    __nv_bfloat16* __restrict__ xmh, __nv_bfloat16* __restrict__ xml)
{
    long gi = (long)blockIdx.x * 256 + threadIdx.x;
    const float* src;
    __nv_bfloat16 *ho, *lo;
    long i = gi;
    const long XOFF = (long)MEMLEN * NROWS * DMODEL;
    if (gi < SC4) {
        if (gi < SC1)       { src = wq;                 ho = wh + WQ_OFF; lo = wl + WQ_OFF; }
        else if (gi < SC2)  { i -= SC1; src = wk;       ho = wh + WK_OFF; lo = wl + WK_OFF; }
        else if (gi < SC3)  { i -= SC2; src = wv;       ho = wh + WV_OFF; lo = wl + WV_OFF; }
        else                { i -= SC3; src = wc;       ho = wh + WC_OFF; lo = wl + WC_OFF; }
    } else if (gi < SC5)    { i -= SC4; src = w1;       ho = wh + W1_OFF; lo = wl + W1_OFF; }
    else if (gi < SC6)      { i -= SC5; src = w2;       ho = wh + W2_OFF; lo = wl + W2_OFF; }
    else if (gi < SC7)      { i -= SC6; src = memory;   ho = xmh;         lo = xml; }
    else                    { i -= SC7; src = x;        ho = xmh + XOFF;  lo = xml + XOFF; }

    float4 v = ((const float4*)src)[i];
    __nv_bfloat162 h0 = split_hi2(v.x, v.y), h1 = split_hi2(v.z, v.w);
    __nv_bfloat162 l0 = split_lo2(v.x, v.y, h0), l1 = split_lo2(v.z, v.w, h1);
    ((__nv_bfloat162*)ho)[i * 2 + 0] = h0;
    ((__nv_bfloat162*)ho)[i * 2 + 1] = h1;
    ((__nv_bfloat162*)lo)[i * 2 + 0] = l0;
    ((__nv_bfloat162*)lo)[i * 2 + 1] = l1;
}

// =======================================================================
// bf16 hi/lo GEMM, cp.async double-buffered.
// BM=128, BN=64, BK=32, 128 threads (4 warps = 2m x 2n, 64x32 warp tile).
// Same 61KB smem -> 3 CTAs/SM; smem bytes per MMA cut 1.33x.
// =======================================================================
#define BM 128
#define BN 64
#define BK 32
#define BKP 40
#define G_AHO 0
#define G_ALO (128 * BKP)
#define G_BHO (256 * BKP)
#define G_BLO (320 * BKP)
#define G_STAGE (384 * BKP)
#define G_SMEM (2 * G_STAGE * 2)            // 61440 bytes

__global__ __launch_bounds__(128) void gemm_bf_kernel(
    const __nv_bfloat16* __restrict__ Ah_g, const __nv_bfloat16* __restrict__ Al_g,
    const __nv_bfloat16* __restrict__ Wh_g, const __nv_bfloat16* __restrict__ Wl_g,
    const float* __restrict__ bias, const float* __restrict__ res,
    float* __restrict__ Cf, __nv_bfloat16* __restrict__ Ch,
    __nv_bfloat16* __restrict__ Cl, int N, int Kd, int relu)
{
    extern __shared__ __align__(16) __nv_bfloat16 gsm[];
    const unsigned sbase = smem_u32(gsm);

    const int tid  = threadIdx.x;
    const int lane = tid & 31;
    const int warp = tid >> 5;          // 0..3
    const int warp_m = warp >> 1;       // 0..1 (64 rows each)
    const int warp_n = warp & 1;        // 0..1 (32 cols each)
    const int bm = blockIdx.y * BM;
    const int bn = blockIdx.x * BN;

    float acc[4][4][4];
#pragma unroll
    for (int i = 0; i < 4; ++i)
#pragma unroll
        for (int j = 0; j < 4; ++j)
#pragma unroll
            for (int l = 0; l < 4; ++l) acc[i][j][l] = 0.0f;

    const int lr16 = lane & 15;
    const int lkh  = (lane >> 4) * 8;
    unsigned aoff[4], boff[2];
#pragma unroll
    for (int mi = 0; mi < 4; ++mi)
        aoff[mi] = (unsigned)((G_AHO + (warp_m * 64 + mi * 16 + lr16) * BKP + lkh) * 2);
#pragma unroll
    for (int nj = 0; nj < 2; ++nj)
        boff[nj] = (unsigned)((G_BHO + (warp_n * 32 + nj * 16 + lr16) * BKP + lkh) * 2);
    const unsigned ALD = (G_ALO - G_AHO) * 2;
    const unsigned BLD = (G_BLO - G_BHO) * 2;

    const int T = Kd / BK;

    // stage load: 1536 chunks of 16B, 12 per thread (128 threads)
    auto issue_tile = [&](int k0, int s) {
        unsigned st = sbase + (unsigned)(s * G_STAGE * 2);
#pragma unroll
        for (int i = 0; i < 12; ++i) {
            int c = tid + i * 128;           // 0..1535
            if (c < 1024) {                  // A: hi then lo
                int half = c >> 9, cc = c & 511;
                int row = cc >> 2, kc = cc & 3;
                long gsrc = (long)(bm + row) * Kd + k0 + kc * 8;
                unsigned d = st + (unsigned)(((half ? G_ALO : G_AHO) + row * BKP + kc * 8) * 2);
                cp_async16(d, (half ? Al_g : Ah_g) + gsrc);
            } else {                         // B: hi then lo
                int cb = c - 1024;
                int half = cb >> 8, cc = cb & 255;
                int row = cc >> 2, kc = cc & 3;
                long gsrc = (long)(bn + row) * Kd + k0 + kc * 8;
                unsigned d = st + (unsigned)(((half ? G_BLO : G_BHO) + row * BKP + kc * 8) * 2);
                cp_async16(d, (half ? Wl_g : Wh_g) + gsrc);
            }
        }
        cp_commit();
    };

    issue_tile(0, 0);

    for (int t = 0; t < T; ++t) {
        cp_wait0();
        __syncthreads();
        if (t + 1 < T) issue_tile((t + 1) * BK, (t + 1) & 1);

        const unsigned stB = sbase + (unsigned)((t & 1) * G_STAGE * 2);
#pragma unroll
        for (int ks = 0; ks < 2; ++ks) {
            const unsigned koff = ks * 32;
            unsigned ah[4][4], al[4][4], bh[2][4], bl[2][4];
#pragma unroll
            for (int mi = 0; mi < 4; ++mi) {
                unsigned a = stB + aoff[mi] + koff;
                ldm_x4(ah[mi], a);
                ldm_x4(al[mi], a + ALD);
            }
#pragma unroll
            for (int nj = 0; nj < 2; ++nj) {
                unsigned bA = stB + boff[nj] + koff;
                ldm_x4(bh[nj], bA);
                ldm_x4(bl[nj], bA + BLD);
            }
#pragma unroll
            for (int mi = 0; mi < 4; ++mi) {
#pragma unroll
                for (int nj = 0; nj < 2; ++nj) {
#pragma unroll
                    for (int s = 0; s < 2; ++s) {
                        float* d = acc[mi][nj * 2 + s];
                        unsigned B0h = bh[nj][s], B1h = bh[nj][s + 2];
                        unsigned B0l = bl[nj][s], B1l = bl[nj][s + 2];
                        mma_bf16(d, ah[mi], B0h, B1h);
                        mma_bf16(d, al[mi], B0h, B1h);
                        mma_bf16(d, ah[mi], B0l, B1l);
                    }
                }
            }
        }
    }

    // epilogue: warp covers 64 rows x 32 cols
    const int mrow = bm + warp_m * 64 + (lane >> 2);
    const int ncol0 = bn + warp_n * 32 + (lane & 3) * 2;
#pragma unroll
    for (int mi = 0; mi < 4; ++mi) {
#pragma unroll
        for (int site = 0; site < 4; ++site) {
            const int m0 = mrow + mi * 16;
            const int n0 = ncol0 + site * 8;
            float c0 = acc[mi][site][0], c1 = acc[mi][site][1];
            float c2 = acc[mi][site][2], c3 = acc[mi][site][3];
            if (bias) {
                float bb0 = bias[n0], bb1 = bias[n0 + 1];
                c0 += bb0; c1 += bb1; c2 += bb0; c3 += bb1;
            }
            if (res) {
                c0 += res[(long)m0 * N + n0];
                c1 += res[(long)m0 * N + n0 + 1];
                c2 += res[(long)(m0 + 8) * N + n0];
                c3 += res[(long)(m0 + 8) * N + n0 + 1];
            }
            if (relu) {
                c0 = fmaxf(c0, 0.f); c1 = fmaxf(c1, 0.f);
                c2 = fmaxf(c2, 0.f); c3 = fmaxf(c3, 0.f);
            }
            if (Cf) {
                *(float2*)&Cf[(long)m0 * N + n0]       = make_float2(c0, c1);
                *(float2*)&Cf[(long)(m0 + 8) * N + n0] = make_float2(c2, c3);
            } else {
                __nv_bfloat162 h0 = split_hi2(c0, c1), h1 = split_hi2(c2, c3);
                __nv_bfloat162 l0 = split_lo2(c0, c1, h0), l1 = split_lo2(c2, c3, h1);
                *(__nv_bfloat162*)&Ch[(long)m0 * N + n0]       = h0;
                *(__nv_bfloat162*)&Ch[(long)(m0 + 8) * N + n0] = h1;
                *(__nv_bfloat162*)&Cl[(long)m0 * N + n0]       = l0;
                *(__nv_bfloat162*)&Cl[(long)(m0 + 8) * N + n0] = l1;
            }
        }
    }
}

// =======================================================================
// Tensor-core flash attention (exact R9/R14 config, best known).
// =======================================================================
#define ATP 72
#define A_QELEMS (64 * ATP)
#define A_STAGE0 (2 * A_QELEMS)
#define A_STAGEE (4 * A_QELEMS)
#define ATTN_SMEM ((A_STAGE0 + 2 * A_STAGEE) * 2)   // 92160 bytes

__global__ __launch_bounds__(128) void attn_tc_kernel(
    const __nv_bfloat16* __restrict__ qh, const __nv_bfloat16* __restrict__ ql,
    const __nv_bfloat16* __restrict__ kh, const __nv_bfloat16* __restrict__ kl,
    const __nv_bfloat16* __restrict__ vh, const __nv_bfloat16* __restrict__ vl,
    const float* __restrict__ mask,
    __nv_bfloat16* __restrict__ avh, __nv_bfloat16* __restrict__ avl)
{
    extern __shared__ __align__(16) __nv_bfloat16 asm_[];
    const unsigned sbase = smem_u32(asm_);

    const int hb = blockIdx.y;
    const int h = hb / BATCH, b = hb % BATCH;
    const int s0 = blockIdx.x * 64;
    const int tid = threadIdx.x;
    const int lane = tid & 31, warp = tid >> 5;

#pragma unroll
    for (int i = 0; i < 8; ++i) {
        int c = tid + i * 128;
        int half = c >> 9, cc = c & 511;
        int row = cc >> 3, kc = cc & 7;
        const __nv_bfloat16* src = (half ? ql : qh) +
            ((long)(s0 + row) * BATCH + b) * DMODEL + h * 64 + kc * 8;
        unsigned d = sbase + (unsigned)((half * A_QELEMS + row * ATP + kc * 8) * 2);
        cp_async16(d, src);
    }
    cp_commit();

    auto issue_kv = [&](int l0, int s) {
        unsigned st = sbase + (unsigned)((A_STAGE0 + s * A_STAGEE) * 2);
#pragma unroll
        for (int i = 0; i < 16; ++i) {
            int c = tid + i * 128;
            int arr = c >> 9, cc = c & 511;
            int row = cc >> 3, kc = cc & 7;
            const __nv_bfloat16* base =
                (arr == 0) ? kh : (arr == 1) ? kl : (arr == 2) ? vh : vl;
            const __nv_bfloat16* src = base +
                ((long)(l0 + row) * BATCH + b) * DMODEL + h * 64 + kc * 8;
            unsigned d = st + (unsigned)((arr * A_QELEMS + row * ATP + kc * 8) * 2);
            cp_async16(d, src);
        }
        cp_commit();
    };

    issue_kv(0, 0);
    cp_wait0();
    __syncthreads();

    unsigned qfh[4][4], qfl[4][4];
    {
        unsigned qb = sbase + (unsigned)(((warp * 16 + (lane & 15)) * ATP + (lane >> 4) * 8) * 2);
        const unsigned qlo = A_QELEMS * 2;
#pragma unroll
        for (int ks = 0; ks < 4; ++ks) {
            ldm_x4(qfh[ks], qb + ks * 32);
            ldm_x4(qfl[ks], qb + ks * 32 + qlo);
        }
    }

    float oacc[8][4];
#pragma unroll
    for (int n = 0; n < 8; ++n)
#pragma unroll
        for (int j = 0; j < 4; ++j) oacc[n][j] = 0.0f;
    float m0 = -1e30f, m1 = -1e30f, ls0 = 0.0f, ls1 = 0.0f;

    const unsigned fragoff = (unsigned)(((lane & 15) * ATP + (lane >> 4) * 8) * 2);
    const unsigned KLD = A_QELEMS * 2;
    const unsigned VOFF = 2 * A_QELEMS * 2;

    const int r0g = s0 + warp * 16 + (lane >> 2);
    const float* mrow0 = mask + (long)r0g * LTOT + (lane & 3) * 2;
    const float* mrow1 = mrow0 + 8L * LTOT;

    const int NIT = LTOT / 64;
    for (int it = 0; it < NIT; ++it) {
        if (it + 1 < NIT) issue_kv((it + 1) * 64, (it + 1) & 1);

        const unsigned stB = sbase + (unsigned)((A_STAGE0 + (it & 1) * A_STAGEE) * 2);
        const unsigned krow = stB + fragoff;
        const unsigned vrow = stB + VOFF + fragoff;
        const int l0 = it * 64;

        float sacc[8][4];
#pragma unroll
        for (int n = 0; n < 8; ++n)
#pragma unroll
            for (int j = 0; j < 4; ++j) sacc[n][j] = 0.0f;

#pragma unroll
        for (int ks = 0; ks < 4; ++ks) {
#pragma unroll
            for (int ng = 0; ng < 4; ++ng) {
                unsigned kbh[4], kbl[4];
                unsigned addr = krow + (unsigned)((ng * 16 * ATP + ks * 16) * 2);
                ldm_x4(kbh, addr);
                ldm_x4(kbl, addr + KLD);
#pragma unroll
                for (int s = 0; s < 2; ++s) {
                    float* d = sacc[ng * 2 + s];
                    mma_bf16(d, qfh[ks], kbh[s], kbh[s + 2]);
                    mma_bf16(d, qfl[ks], kbh[s], kbh[s + 2]);
                    mma_bf16(d, qfh[ks], kbl[s], kbl[s + 2]);
                }
            }
        }

        float mx0 = -1e30f, mx1 = -1e30f;
#pragma unroll
        for (int n = 0; n < 8; ++n) {
            float2 mk0 = *(const float2*)&mrow0[l0 + n * 8];
            float2 mk1 = *(const float2*)&mrow1[l0 + n * 8];
            sacc[n][0] = sacc[n][0] * 0.125f + mk0.x;
            sacc[n][1] = sacc[n][1] * 0.125f + mk0.y;
            sacc[n][2] = sacc[n][2] * 0.125f + mk1.x;
            sacc[n][3] = sacc[n][3] * 0.125f + mk1.y;
            mx0 = fmaxf(mx0, fmaxf(sacc[n][0], sacc[n][1]));
            mx1 = fmaxf(mx1, fmaxf(sacc[n][2], sacc[n][3]));
        }
        mx0 = fmaxf(mx0, __shfl_xor_sync(0xffffffffu, mx0, 1));
        mx0 = fmaxf(mx0, __shfl_xor_sync(0xffffffffu, mx0, 2));
        mx1 = fmaxf(mx1, __shfl_xor_sync(0xffffffffu, mx1, 1));
        mx1 = fmaxf(mx1, __shfl_xor_sync(0xffffffffu, mx1, 2));
        float m0n = fmaxf(m0, mx0), m1n = fmaxf(m1, mx1);
        float c0 = __expf(m0 - m0n), c1 = __expf(m1 - m1n);
        m0 = m0n; m1 = m1n;

        float ps0 = 0.0f, ps1 = 0.0f;
#pragma unroll
        for (int n = 0; n < 8; ++n) {
            sacc[n][0] = __expf(sacc[n][0] - m0n);
            sacc[n][1] = __expf(sacc[n][1] - m0n);
            sacc[n][2] = __expf(sacc[n][2] - m1n);
            sacc[n][3] = __expf(sacc[n][3] - m1n);
            ps0 += sacc[n][0] + sacc[n][1];
            ps1 += sacc[n][2] + sacc[n][3];
        }
        ps0 += __shfl_xor_sync(0xffffffffu, ps0, 1);
        ps0 += __shfl_xor_sync(0xffffffffu, ps0, 2);
        ps1 += __shfl_xor_sync(0xffffffffu, ps1, 1);
        ps1 += __shfl_xor_sync(0xffffffffu, ps1, 2);
        ls0 = ls0 * c0 + ps0;
        ls1 = ls1 * c1 + ps1;

#pragma unroll
        for (int n = 0; n < 8; ++n) {
            oacc[n][0] *= c0; oacc[n][1] *= c0;
            oacc[n][2] *= c1; oacc[n][3] *= c1;
        }

        unsigned pah[4][4], pal[4][4];
#pragma unroll
        for (int kp = 0; kp < 4; ++kp) {
            const float* t0 = sacc[2 * kp];
            const float* t1 = sacc[2 * kp + 1];
            pah[kp][0] = pack_hi2(t0[0], t0[1]);
            pah[kp][1] = pack_hi2(t0[2], t0[3]);
            pah[kp][2] = pack_hi2(t1[0], t1[1]);
            pah[kp][3] = pack_hi2(t1[2], t1[3]);
            pal[kp][0] = pack_lo2(t0[0], t0[1], pah[kp][0]);
            pal[kp][1] = pack_lo2(t0[2], t0[3], pah[kp][1]);
            pal[kp][2] = pack_lo2(t1[0], t1[1], pah[kp][2]);
            pal[kp][3] = pack_lo2(t1[2], t1[3], pah[kp][3]);
        }

#pragma unroll
        for (int kp = 0; kp < 4; ++kp) {
#pragma unroll
            for (int ng = 0; ng < 4; ++ng) {
                unsigned vbh[4], vbl[4];
                unsigned addr = vrow + (unsigned)((kp * 16 * ATP + ng * 16) * 2);
                ldm_x4_t(vbh, addr);
                ldm_x4_t(vbl, addr + KLD);
#pragma unroll
                for (int s = 0; s < 2; ++s) {
                    float* d = oacc[ng * 2 + s];
                    mma_bf16(d, pah[kp], vbh[s * 2], vbh[s * 2 + 1]);
                    mma_bf16(d, pal[kp], vbh[s * 2], vbh[s * 2 + 1]);
                    mma_bf16(d, pah[kp], vbl[s * 2], vbl[s * 2 + 1]);
                }
            }
        }

        if (it + 1 < NIT) {
            cp_wait0();
            __syncthreads();
        }
    }

    float inv0 = 1.0f / ls0, inv1 = 1.0f / ls1;
#pragma unroll
    for (int n = 0; n < 8; ++n) {
        int col = h * 64 + n * 8 + (lane & 3) * 2;
        long i0 = ((long)r0g * BATCH + b) * DMODEL + col;
        long i1 = ((long)(r0g + 8) * BATCH + b) * DMODEL + col;
        float a0 = oacc[n][0] * inv0, a1 = oacc[n][1] * inv0;
        float a2 = oacc[n][2] * inv1, a3 = oacc[n][3] * inv1;
        __nv_bfloat162 h0 = split_hi2(a0, a1), h1 = split_hi2(a2, a3);
        __nv_bfloat162 l0 = split_lo2(a0, a1, h0), l1 = split_lo2(a2, a3, h1);
        *(__nv_bfloat162*)&avh[i0] = h0;
        *(__nv_bfloat162*)&avh[i1] = h1;
        *(__nv_bfloat162*)&avl[i0] = l0;
        *(__nv_bfloat162*)&avl[i1] = l1;
    }
}

// ---------------- LayerNorm over D=1024 (+ optional hi/lo bf16 out) ----
__global__ __launch_bounds__(256) void ln_kernel(
    const float* __restrict__ in, float* __restrict__ out,
    const float* __restrict__ g, const float* __restrict__ bta,
    __nv_bfloat16* __restrict__ oh, __nv_bfloat16* __restrict__ ol)
{
    const int row = blockIdx.x;
    const float* x = in + (long)row * DMODEL;
    const int tid = threadIdx.x;
    float v[4];
    float s = 0.0f, s2 = 0.0f;
#pragma unroll
    for (int i = 0; i < 4; ++i) {
        v[i] = x[tid + i * 256];
        s += v[i];
        s2 += v[i] * v[i];
    }
    __shared__ float rs[8], rs2[8];
#pragma unroll
    for (int o = 16; o > 0; o >>= 1) {
        s  += __shfl_xor_sync(0xffffffffu, s, o);
        s2 += __shfl_xor_sync(0xffffffffu, s2, o);
    }
    if ((tid & 31) == 0) { rs[tid >> 5] = s; rs2[tid >> 5] = s2; }
    __syncthreads();
    if (tid < 32) {
        s  = (tid < 8) ? rs[tid]  : 0.0f;
        s2 = (tid < 8) ? rs2[tid] : 0.0f;
#pragma unroll
        for (int o = 4; o > 0; o >>= 1) {
            s  += __shfl_xor_sync(0xffffffffu, s, o);
            s2 += __shfl_xor_sync(0xffffffffu, s2, o);
        }
        if (tid == 0) { rs[0] = s; rs2[0] = s2; }
    }
    __syncthreads();
    float mu  = rs[0] * (1.0f / DMODEL);
    float var = rs2[0] * (1.0f / DMODEL) - mu * mu;
    float inv = rsqrtf(var + 1e-5f);
#pragma unroll
    for (int i = 0; i < 4; ++i) {
        int c = tid + i * 256;
        float y = (v[i] - mu) * inv * g[c] + bta[c];
        out[(long)row * DMODEL + c] = y;
        if (oh) {
            __nv_bfloat16 hb = __float2bfloat16_rn(y);
            oh[(long)row * DMODEL + c] = hb;
            ol[(long)row * DMODEL + c] =
                __float2bfloat16_rn(y - __bfloat162float(hb));
        }
    }
}

// ---------------- launch ----------------
extern "C" void kernel_launch(void* const* d_in, const int* in_sizes, int n_in,
                              void* d_out, int out_size)
{
    const float* x      = (const float*)d_in[0];
    const float* mask   = (const float*)d_in[1];
    const float* memory = (const float*)d_in[2];

    int o = 3;
    if (n_in >= 16 && in_sizes[3] == 1) o = 4;
    const float* wq   = (const float*)d_in[o + 0];
    const float* wk   = (const float*)d_in[o + 1];
    const float* wv   = (const float*)d_in[o + 2];
    const float* wc   = (const float*)d_in[o + 3];
    const float* w1   = (const float*)d_in[o + 4];
    const float* b1   = (const float*)d_in[o + 5];
    const float* w2   = (const float*)d_in[o + 6];
    const float* b2   = (const float*)d_in[o + 7];
    const float* ln1g = (const float*)d_in[o + 8];
    const float* ln1b = (const float*)d_in[o + 9];
    const float* ln2g = (const float*)d_in[o + 10];
    const float* ln2b = (const float*)d_in[o + 11];
    float* out = (float*)d_out;

    float *upre, *u;
    __nv_bfloat16 *wh, *wl, *xmh, *xml, *qh, *ql, *kh, *kl, *vh, *vl;
    __nv_bfloat16 *avh, *avl, *uh, *ul, *ffh, *ffl;
    cudaGetSymbolAddress((void**)&upre, g_upre);
    cudaGetSymbolAddress((void**)&u,    g_u);
    cudaGetSymbolAddress((void**)&wh,   g_wh);
    cudaGetSymbolAddress((void**)&wl,   g_wl);
    cudaGetSymbolAddress((void**)&xmh,  g_xmh);
    cudaGetSymbolAddress((void**)&xml,  g_xml);
    cudaGetSymbolAddress((void**)&qh,   g_qh);
    cudaGetSymbolAddress((void**)&ql,   g_ql);
    cudaGetSymbolAddress((void**)&kh,   g_kh);
    cudaGetSymbolAddress((void**)&kl,   g_kl);
    cudaGetSymbolAddress((void**)&vh,   g_vh);
    cudaGetSymbolAddress((void**)&vl,   g_vl);
    cudaGetSymbolAddress((void**)&avh,  g_avh);
    cudaGetSymbolAddress((void**)&avl,  g_avl);
    cudaGetSymbolAddress((void**)&uh,   g_uh);
    cudaGetSymbolAddress((void**)&ul,   g_ul);
    cudaGetSymbolAddress((void**)&ffh,  g_ffh);
    cudaGetSymbolAddress((void**)&ffl,  g_ffl);

    cudaFuncSetAttribute(gemm_bf_kernel,
                         cudaFuncAttributeMaxDynamicSharedMemorySize, G_SMEM);
    cudaFuncSetAttribute(attn_tc_kernel,
                         cudaFuncAttributeMaxDynamicSharedMemorySize, ATTN_SMEM);

    dim3 gthr(128);
    const long XOFF = (long)MEMLEN * NROWS * DMODEL;

    // ---- ONE fused convert launch for all 8 regions ----
    fused_split_kernel<<<SC8 / 256, 256>>>(
        wq, wk, wv, wc, w1, w2, memory, x, wh, wl, xmh, xml);

    // ---- QKV GEMMs (bf16 out) ----
    gemm_bf_kernel<<<dim3(DMODEL / BN, NROWS / BM), gthr, G_SMEM>>>(
        xmh + XOFF, xml + XOFF, wh + WQ_OFF, wl + WQ_OFF,
        nullptr, nullptr, nullptr, qh, ql, DMODEL, DMODEL, 0);
    gemm_bf_kernel<<<dim3(DMODEL / BN, KVROWS / BM), gthr, G_SMEM>>>(
        xmh, xml, wh + WK_OFF, wl + WK_OFF,
        nullptr, nullptr, nullptr, kh, kl, DMODEL, DMODEL, 0);
    gemm_bf_kernel<<<dim3(DMODEL / BN, KVROWS / BM), gthr, G_SMEM>>>(
        xmh, xml, wh + WV_OFF, wl + WV_OFF,
        nullptr, nullptr, nullptr, vh, vl, DMODEL, DMODEL, 0);

    // ---- attention ----
    attn_tc_kernel<<<dim3(SEQ / 64, HEADS * BATCH), 128, ATTN_SMEM>>>(
        qh, ql, kh, kl, vh, vl, mask, avh, avl);

    // ---- u_pre = av @ wc^T + x (fp32), LN1 -> u (fp32 + bf16) ----
    gemm_bf_kernel<<<dim3(DMODEL / BN, NROWS / BM), gthr, G_SMEM>>>(
        avh, avl, wh + WC_OFF, wl + WC_OFF,
        nullptr, x, upre, nullptr, nullptr, DMODEL, DMODEL, 0);
    ln_kernel<<<NROWS, 256>>>(upre, u, ln1g, ln1b, uh, ul);

    // ---- ff = relu(u @ w1^T + b1) (bf16 out) ----
    gemm_bf_kernel<<<dim3(MFF / BN, NROWS / BM), gthr, G_SMEM>>>(
        uh, ul, wh + W1_OFF, wl + W1_OFF,
        b1, nullptr, nullptr, ffh, ffl, MFF, DMODEL, 1);

    // ---- z_pre = ff @ w2^T + b2 + u (fp32), LN2 in-place ----
    gemm_bf_kernel<<<dim3(DMODEL / BN, NROWS / BM), gthr, G_SMEM>>>(
        ffh, ffl, wh + W2_OFF, wl + W2_OFF,
        b2, u, out, nullptr, nullptr, DMODEL, MFF, 0);
    ln_kernel<<<NROWS, 256>>>(out, out, ln2g, ln2b, nullptr, nullptr);
}

// round 17
// speedup vs baseline: 1.0178x; 1.0178x over previous
#include <cuda_runtime.h>
#include <cuda_bf16.h>
#include <math.h>

// Problem constants
#define HEADS 16
#define DMODEL 1024
#define KDIM 64
#define MFF 4096
#define MEMLEN 3
#define SEQ 512
#define BATCH 4
#define NROWS (SEQ * BATCH)            // 2048
#define LTOT ((MEMLEN + 1) * SEQ)      // 2048
#define KVROWS (LTOT * BATCH)          // 8192
#define HKD (HEADS * KDIM * DMODEL)    // 1048576 elems per qkv/c weight

// ---------------- scratch (no allocation allowed) ----------------
__device__ float g_upre[NROWS * DMODEL];
__device__ float g_u[NROWS * DMODEL];
__device__ __nv_bfloat16 g_wh[12 * 1024 * 1024];
__device__ __nv_bfloat16 g_wl[12 * 1024 * 1024];
__device__ __nv_bfloat16 g_xmh[KVROWS * DMODEL];
__device__ __nv_bfloat16 g_xml[KVROWS * DMODEL];
__device__ __nv_bfloat16 g_qh[NROWS * DMODEL];
__device__ __nv_bfloat16 g_ql[NROWS * DMODEL];
__device__ __nv_bfloat16 g_kh[KVROWS * DMODEL];
__device__ __nv_bfloat16 g_kl[KVROWS * DMODEL];
__device__ __nv_bfloat16 g_vh[KVROWS * DMODEL];
__device__ __nv_bfloat16 g_vl[KVROWS * DMODEL];
__device__ __nv_bfloat16 g_avh[NROWS * DMODEL];
__device__ __nv_bfloat16 g_avl[NROWS * DMODEL];
__device__ __nv_bfloat16 g_uh[NROWS * DMODEL];
__device__ __nv_bfloat16 g_ul[NROWS * DMODEL];
__device__ __nv_bfloat16 g_ffh[NROWS * MFF];
__device__ __nv_bfloat16 g_ffl[NROWS * MFF];

#define WQ_OFF 0
#define WK_OFF (1 * HKD)
#define WV_OFF (2 * HKD)
#define WC_OFF (3 * HKD)
#define W1_OFF (4 * HKD)
#define W2_OFF (8 * HKD)

// ---------------- helpers ----------------
__device__ __forceinline__ unsigned smem_u32(const void* p) {
    return (unsigned)__cvta_generic_to_shared(p);
}
__device__ __forceinline__ void cp_async16(unsigned dst, const void* src) {
    asm volatile("cp.async.cg.shared.global [%0], [%1], 16;" :: "r"(dst), "l"(src));
}
__device__ __forceinline__ void cp_commit() {
    asm volatile("cp.async.commit_group;");
}
__device__ __forceinline__ void cp_wait0() {
    asm volatile("cp.async.wait_group 0;");
}
__device__ __forceinline__ void ldm_x4(unsigned* r, unsigned addr) {
    asm volatile("ldmatrix.sync.aligned.m8n8.x4.shared.b16 {%0,%1,%2,%3}, [%4];"
                 : "=r"(r[0]), "=r"(r[1]), "=r"(r[2]), "=r"(r[3]) : "r"(addr));
}
__device__ __forceinline__ void ldm_x4_t(unsigned* r, unsigned addr) {
    asm volatile("ldmatrix.sync.aligned.m8n8.x4.trans.shared.b16 {%0,%1,%2,%3}, [%4];"
                 : "=r"(r[0]), "=r"(r[1]), "=r"(r[2]), "=r"(r[3]) : "r"(addr));
}
__device__ __forceinline__ void mma_bf16(float* d, const unsigned* a,
                                         unsigned b0, unsigned b1) {
    asm volatile("mma.sync.aligned.m16n8k16.row.col.f32.bf16.bf16.f32 "
                 "{%0,%1,%2,%3}, {%4,%5,%6,%7}, {%8,%9}, {%0,%1,%2,%3};"
                 : "+f"(d[0]), "+f"(d[1]), "+f"(d[2]), "+f"(d[3])
                 : "r"(a[0]), "r"(a[1]), "r"(a[2]), "r"(a[3]), "r"(b0), "r"(b1));
}
__device__ __forceinline__ __nv_bfloat162 split_hi2(float x, float y) {
    return __nv_bfloat162(__float2bfloat16_rn(x), __float2bfloat16_rn(y));
}
__device__ __forceinline__ __nv_bfloat162 split_lo2(float x, float y,
                                                    __nv_bfloat162 h) {
    return __nv_bfloat162(
        __float2bfloat16_rn(x - __bfloat162float(h.x)),
        __float2bfloat16_rn(y - __bfloat162float(h.y)));
}
__device__ __forceinline__ unsigned pack_hi2(float a, float b) {
    __nv_bfloat162 t = split_hi2(a, b);
    return reinterpret_cast<unsigned&>(t);
}
__device__ __forceinline__ unsigned pack_lo2(float a, float b, unsigned hibits) {
    __nv_bfloat162 h = reinterpret_cast<__nv_bfloat162&>(hibits);
    __nv_bfloat162 t = split_lo2(a, b, h);
    return reinterpret_cast<unsigned&>(t);
}

// ---------------- fused fp32 -> (hi,lo) bf16 split ----------------
#define SC1 262144
#define SC2 524288
#define SC3 786432
#define SC4 1048576
#define SC5 2097152
#define SC6 3145728
#define SC7 4718592
#define SC8 5242880

__global__ __launch_bounds__(256) void fused_split_kernel(
    const float* __restrict__ wq, const float* __restrict__ wk,
    const float* __restrict__ wv, const float* __restrict__ wc,
    const float* __restrict__ w1, const float* __restrict__ w2,
    const float* __restrict__ memory, const float* __restrict__ x,
    __nv_bfloat16* __restrict__ wh, __nv_bfloat16* __restrict__ wl,
    __nv_bfloat16* __restrict__ xmh, __nv_bfloat16* __restrict__ xml)
{
    long gi = (long)blockIdx.x * 256 + threadIdx.x;
    const float* src;
    __nv_bfloat16 *ho, *lo;
    long i = gi;
    const long XOFF = (long)MEMLEN * NROWS * DMODEL;
    if (gi < SC4) {
        if (gi < SC1)       { src = wq;                 ho = wh + WQ_OFF; lo = wl + WQ_OFF; }
        else if (gi < SC2)  { i -= SC1; src = wk;       ho = wh + WK_OFF; lo = wl + WK_OFF; }
        else if (gi < SC3)  { i -= SC2; src = wv;       ho = wh + WV_OFF; lo = wl + WV_OFF; }
        else                { i -= SC3; src = wc;       ho = wh + WC_OFF; lo = wl + WC_OFF; }
    } else if (gi < SC5)    { i -= SC4; src = w1;       ho = wh + W1_OFF; lo = wl + W1_OFF; }
    else if (gi < SC6)      { i -= SC5; src = w2;       ho = wh + W2_OFF; lo = wl + W2_OFF; }
    else if (gi < SC7)      { i -= SC6; src = memory;   ho = xmh;         lo = xml; }
    else                    { i -= SC7; src = x;        ho = xmh + XOFF;  lo = xml + XOFF; }

    float4 v = ((const float4*)src)[i];
    __nv_bfloat162 h0 = split_hi2(v.x, v.y), h1 = split_hi2(v.z, v.w);
    __nv_bfloat162 l0 = split_lo2(v.x, v.y, h0), l1 = split_lo2(v.z, v.w, h1);
    ((__nv_bfloat162*)ho)[i * 2 + 0] = h0;
    ((__nv_bfloat162*)ho)[i * 2 + 1] = h1;
    ((__nv_bfloat162*)lo)[i * 2 + 0] = l0;
    ((__nv_bfloat162*)lo)[i * 2 + 1] = l1;
}

// =======================================================================
// bf16 hi/lo GEMM, cp.async double-buffered (exact R14 config, best known).
// BM=128, BN=64, BK=32, 256 threads (8 warps = 4m x 2n).
// =======================================================================
#define BM 128
#define BN 64
#define BK 32
#define BKP 40
#define G_AHO 0
#define G_ALO (128 * BKP)
#define G_BHO (256 * BKP)
#define G_BLO (320 * BKP)
#define G_STAGE (384 * BKP)
#define G_SMEM (2 * G_STAGE * 2)            // 61440 bytes

__global__ __launch_bounds__(256) void gemm_bf_kernel(
    const __nv_bfloat16* __restrict__ Ah_g, const __nv_bfloat16* __restrict__ Al_g,
    const __nv_bfloat16* __restrict__ Wh_g, const __nv_bfloat16* __restrict__ Wl_g,
    const float* __restrict__ bias, const float* __restrict__ res,
    float* __restrict__ Cf, __nv_bfloat16* __restrict__ Ch,
    __nv_bfloat16* __restrict__ Cl, int N, int Kd, int relu)
{
    extern __shared__ __align__(16) __nv_bfloat16 gsm[];
    const unsigned sbase = smem_u32(gsm);

    const int tid  = threadIdx.x;
    const int lane = tid & 31;
    const int warp = tid >> 5;
    const int warp_m = warp >> 1;
    const int warp_n = warp & 1;
    const int bm = blockIdx.y * BM;
    const int bn = blockIdx.x * BN;

    const int b_row0 = tid >> 2;
    const int b_kc0  = tid & 3;

    float acc[2][4][4];
#pragma unroll
    for (int i = 0; i < 2; ++i)
#pragma unroll
        for (int j = 0; j < 4; ++j)
#pragma unroll
            for (int l = 0; l < 4; ++l) acc[i][j][l] = 0.0f;

    const int lr16 = lane & 15;
    const int lkh  = (lane >> 4) * 8;
    unsigned aoff[2], boff[2];
#pragma unroll
    for (int mi = 0; mi < 2; ++mi)
        aoff[mi] = (unsigned)((G_AHO + (warp_m * 32 + mi * 16 + lr16) * BKP + lkh) * 2);
#pragma unroll
    for (int nj = 0; nj < 2; ++nj)
        boff[nj] = (unsigned)((G_BHO + (warp_n * 32 + nj * 16 + lr16) * BKP + lkh) * 2);
    const unsigned ALD = (G_ALO - G_AHO) * 2;
    const unsigned BLD = (G_BLO - G_BHO) * 2;

    const int T = Kd / BK;

    auto issue_tile = [&](int k0, int s) {
        unsigned st = sbase + (unsigned)(s * G_STAGE * 2);
#pragma unroll
        for (int i = 0; i < 2; ++i) {
            int c = tid + i * 256;
            int row = c >> 2, kc = c & 3;
            long gsrc = (long)(bm + row) * Kd + k0 + kc * 8;
            unsigned d = st + (unsigned)((row * BKP + kc * 8) * 2);
            cp_async16(d + G_AHO * 2, Ah_g + gsrc);
            cp_async16(d + G_ALO * 2, Al_g + gsrc);
        }
        {
            int row = b_row0, kc = b_kc0;
            long gsrc = (long)(bn + row) * Kd + k0 + kc * 8;
            unsigned d = st + (unsigned)((row * BKP + kc * 8) * 2);
            cp_async16(d + G_BHO * 2, Wh_g + gsrc);
            cp_async16(d + G_BLO * 2, Wl_g + gsrc);
        }
        cp_commit();
    };

    issue_tile(0, 0);

    for (int t = 0; t < T; ++t) {
        cp_wait0();
        __syncthreads();
        if (t + 1 < T) issue_tile((t + 1) * BK, (t + 1) & 1);

        const unsigned stB = sbase + (unsigned)((t & 1) * G_STAGE * 2);
#pragma unroll
        for (int ks = 0; ks < 2; ++ks) {
            const unsigned koff = ks * 32;
            unsigned ah[2][4], al[2][4], bh[2][4], bl[2][4];
#pragma unroll
            for (int mi = 0; mi < 2; ++mi) {
                unsigned a = stB + aoff[mi] + koff;
                ldm_x4(ah[mi], a);
                ldm_x4(al[mi], a + ALD);
            }
#pragma unroll
            for (int nj = 0; nj < 2; ++nj) {
                unsigned bA = stB + boff[nj] + koff;
                ldm_x4(bh[nj], bA);
                ldm_x4(bl[nj], bA + BLD);
            }
#pragma unroll
            for (int mi = 0; mi < 2; ++mi) {
#pragma unroll
                for (int nj = 0; nj < 2; ++nj) {
#pragma unroll
                    for (int s = 0; s < 2; ++s) {
                        float* d = acc[mi][nj * 2 + s];
                        unsigned B0h = bh[nj][s], B1h = bh[nj][s + 2];
                        unsigned B0l = bl[nj][s], B1l = bl[nj][s + 2];
                        mma_bf16(d, ah[mi], B0h, B1h);
                        mma_bf16(d, al[mi], B0h, B1h);
                        mma_bf16(d, ah[mi], B0l, B1l);
                    }
                }
            }
        }
    }

    const int mrow = bm + warp_m * 32 + (lane >> 2);
    const int ncol0 = bn + warp_n * 32 + (lane & 3) * 2;
#pragma unroll
    for (int mi = 0; mi < 2; ++mi) {
#pragma unroll
        for (int site = 0; site < 4; ++site) {
            const int m0 = mrow + mi * 16;
            const int n0 = ncol0 + site * 8;
            float c0 = acc[mi][site][0], c1 = acc[mi][site][1];
            float c2 = acc[mi][site][2], c3 = acc[mi][site][3];
            if (bias) {
                float bb0 = bias[n0], bb1 = bias[n0 + 1];
                c0 += bb0; c1 += bb1; c2 += bb0; c3 += bb1;
            }
            if (res) {
                c0 += res[(long)m0 * N + n0];
                c1 += res[(long)m0 * N + n0 + 1];
                c2 += res[(long)(m0 + 8) * N + n0];
                c3 += res[(long)(m0 + 8) * N + n0 + 1];
            }
            if (relu) {
                c0 = fmaxf(c0, 0.f); c1 = fmaxf(c1, 0.f);
                c2 = fmaxf(c2, 0.f); c3 = fmaxf(c3, 0.f);
            }
            if (Cf) {
                *(float2*)&Cf[(long)m0 * N + n0]       = make_float2(c0, c1);
                *(float2*)&Cf[(long)(m0 + 8) * N + n0] = make_float2(c2, c3);
            } else {
                __nv_bfloat162 h0 = split_hi2(c0, c1), h1 = split_hi2(c2, c3);
                __nv_bfloat162 l0 = split_lo2(c0, c1, h0), l1 = split_lo2(c2, c3, h1);
                *(__nv_bfloat162*)&Ch[(long)m0 * N + n0]       = h0;
                *(__nv_bfloat162*)&Ch[(long)(m0 + 8) * N + n0] = h1;
                *(__nv_bfloat162*)&Cl[(long)m0 * N + n0]       = l0;
                *(__nv_bfloat162*)&Cl[(long)(m0 + 8) * N + n0] = l1;
            }
        }
    }
}

// =======================================================================
// Fused K+V GEMM: loads A (xm) tiles once, computes K and V outputs.
// BM=128, BN=64, BK=32, 128 threads (4 warps = 2m x 2n, 64x32 warp tiles).
// stage: Ah Al (128x40) | BKh BKl BVh BVl (64x40 each) = 40960B, 2 stages.
// =======================================================================
#define F_AH 0
#define F_AL (128 * BKP)
#define F_BKH (256 * BKP)
#define F_BKL (F_BKH + 64 * BKP)
#define F_BVH (F_BKL + 64 * BKP)
#define F_BVL (F_BVH + 64 * BKP)
#define F_STAGE (512 * BKP)                  // 20480 elems = 40960B
#define F_SMEM (2 * F_STAGE * 2)             // 81920 bytes

__global__ __launch_bounds__(128) void gemm_kv_kernel(
    const __nv_bfloat16* __restrict__ Ah_g, const __nv_bfloat16* __restrict__ Al_g,
    const __nv_bfloat16* __restrict__ WKh_g, const __nv_bfloat16* __restrict__ WKl_g,
    const __nv_bfloat16* __restrict__ WVh_g, const __nv_bfloat16* __restrict__ WVl_g,
    __nv_bfloat16* __restrict__ Kh, __nv_bfloat16* __restrict__ Kl,
    __nv_bfloat16* __restrict__ Vh, __nv_bfloat16* __restrict__ Vl,
    int N, int Kd)
{
    extern __shared__ __align__(16) __nv_bfloat16 fsm[];
    const unsigned sbase = smem_u32(fsm);

    const int tid  = threadIdx.x;
    const int lane = tid & 31;
    const int warp = tid >> 5;          // 0..3
    const int warp_m = warp >> 1;       // 0..1 (64 rows)
    const int warp_n = warp & 1;        // 0..1 (32 cols)
    const int bm = blockIdx.y * BM;
    const int bn = blockIdx.x * BN;

    float acck[4][4][4], accv[4][4][4];
#pragma unroll
    for (int i = 0; i < 4; ++i)
#pragma unroll
        for (int j = 0; j < 4; ++j)
#pragma unroll
            for (int l = 0; l < 4; ++l) { acck[i][j][l] = 0.0f; accv[i][j][l] = 0.0f; }

    const int lr16 = lane & 15;
    const int lkh  = (lane >> 4) * 8;
    unsigned aoff[4], bkoff[2], bvoff[2];
#pragma unroll
    for (int mi = 0; mi < 4; ++mi)
        aoff[mi] = (unsigned)((F_AH + (warp_m * 64 + mi * 16 + lr16) * BKP + lkh) * 2);
#pragma unroll
    for (int nj = 0; nj < 2; ++nj) {
        bkoff[nj] = (unsigned)((F_BKH + (warp_n * 32 + nj * 16 + lr16) * BKP + lkh) * 2);
        bvoff[nj] = (unsigned)((F_BVH + (warp_n * 32 + nj * 16 + lr16) * BKP + lkh) * 2);
    }
    const unsigned LOD = (unsigned)(64 * BKP * 2) * 2;   // hi->lo within B pairs? no:
    // lo offsets: A: F_AL-F_AH = 128*BKP elems; B: 64*BKP elems
    const unsigned ALD = (unsigned)((F_AL - F_AH) * 2);
    const unsigned BLD = (unsigned)((F_BKL - F_BKH) * 2);  // same gap for V pair

    const int T = Kd / BK;

    // 2048 chunks of 16B, 16 per thread
    auto issue_tile = [&](int k0, int s) {
        unsigned st = sbase + (unsigned)(s * F_STAGE * 2);
#pragma unroll
        for (int i = 0; i < 16; ++i) {
            int c = tid + i * 128;
            if (c < 1024) {                  // A: hi(0..511), lo(512..1023)
                int half = c >> 9, cc = c & 511;
                int row = cc >> 2, kc = cc & 3;
                long gsrc = (long)(bm + row) * Kd + k0 + kc * 8;
                unsigned d = st + (unsigned)(((half ? F_AL : F_AH) + row * BKP + kc * 8) * 2);
                cp_async16(d, (half ? Al_g : Ah_g) + gsrc);
            } else {                         // B: 4 arrays x 256 chunks
                int cb = c - 1024;
                int which = cb >> 8, cc = cb & 255;
                int row = cc >> 2, kc = cc & 3;
                const __nv_bfloat16* base =
                    (which == 0) ? WKh_g : (which == 1) ? WKl_g :
                    (which == 2) ? WVh_g : WVl_g;
                unsigned arrb = (which == 0) ? F_BKH : (which == 1) ? F_BKL :
                                (which == 2) ? F_BVH : F_BVL;
                long gsrc = (long)(bn + row) * Kd + k0 + kc * 8;
                unsigned d = st + (unsigned)((arrb + row * BKP + kc * 8) * 2);
                cp_async16(d, base + gsrc);
            }
        }
        cp_commit();
    };

    issue_tile(0, 0);

    for (int t = 0; t < T; ++t) {
        cp_wait0();
        __syncthreads();
        if (t + 1 < T) issue_tile((t + 1) * BK, (t + 1) & 1);

        const unsigned stB = sbase + (unsigned)((t & 1) * F_STAGE * 2);
#pragma unroll
        for (int ks = 0; ks < 2; ++ks) {
            const unsigned koff = ks * 32;
            unsigned ah[4][4], al[4][4];
#pragma unroll
            for (int mi = 0; mi < 4; ++mi) {
                unsigned a = stB + aoff[mi] + koff;
                ldm_x4(ah[mi], a);
                ldm_x4(al[mi], a + ALD);
            }
            // ---- K output ----
            {
                unsigned bh[2][4], bl[2][4];
#pragma unroll
                for (int nj = 0; nj < 2; ++nj) {
                    unsigned bA = stB + bkoff[nj] + koff;
                    ldm_x4(bh[nj], bA);
                    ldm_x4(bl[nj], bA + BLD);
                }
#pragma unroll
                for (int mi = 0; mi < 4; ++mi)
#pragma unroll
                    for (int nj = 0; nj < 2; ++nj)
#pragma unroll
                        for (int s = 0; s < 2; ++s) {
                            float* d = acck[mi][nj * 2 + s];
                            unsigned B0h = bh[nj][s], B1h = bh[nj][s + 2];
                            unsigned B0l = bl[nj][s], B1l = bl[nj][s + 2];
                            mma_bf16(d, ah[mi], B0h, B1h);
                            mma_bf16(d, al[mi], B0h, B1h);
                            mma_bf16(d, ah[mi], B0l, B1l);
                        }
            }
            // ---- V output ----
            {
                unsigned bh[2][4], bl[2][4];
#pragma unroll
                for (int nj = 0; nj < 2; ++nj) {
                    unsigned bA = stB + bvoff[nj] + koff;
                    ldm_x4(bh[nj], bA);
                    ldm_x4(bl[nj], bA + BLD);
                }
#pragma unroll
                for (int mi = 0; mi < 4; ++mi)
#pragma unroll
                    for (int nj = 0; nj < 2; ++nj)
#pragma unroll
                        for (int s = 0; s < 2; ++s) {
                            float* d = accv[mi][nj * 2 + s];
                            unsigned B0h = bh[nj][s], B1h = bh[nj][s + 2];
                            unsigned B0l = bl[nj][s], B1l = bl[nj][s + 2];
                            mma_bf16(d, ah[mi], B0h, B1h);
                            mma_bf16(d, al[mi], B0h, B1h);
                            mma_bf16(d, ah[mi], B0l, B1l);
                        }
            }
        }
    }

    // epilogue: warp covers 64 rows x 32 cols; write K and V (bf16 hi/lo)
    const int mrow = bm + warp_m * 64 + (lane >> 2);
    const int ncol0 = bn + warp_n * 32 + (lane & 3) * 2;
#pragma unroll
    for (int mi = 0; mi < 4; ++mi) {
#pragma unroll
        for (int site = 0; site < 4; ++site) {
            const int m0 = mrow + mi * 16;
            const int n0 = ncol0 + site * 8;
            {
                float c0 = acck[mi][site][0], c1 = acck[mi][site][1];
                float c2 = acck[mi][site][2], c3 = acck[mi][site][3];
                __nv_bfloat162 h0 = split_hi2(c0, c1), h1 = split_hi2(c2, c3);
                __nv_bfloat162 l0 = split_lo2(c0, c1, h0), l1 = split_lo2(c2, c3, h1);
                *(__nv_bfloat162*)&Kh[(long)m0 * N + n0]       = h0;
                *(__nv_bfloat162*)&Kh[(long)(m0 + 8) * N + n0] = h1;
                *(__nv_bfloat162*)&Kl[(long)m0 * N + n0]       = l0;
                *(__nv_bfloat162*)&Kl[(long)(m0 + 8) * N + n0] = l1;
            }
            {
                float c0 = accv[mi][site][0], c1 = accv[mi][site][1];
                float c2 = accv[mi][site][2], c3 = accv[mi][site][3];
                __nv_bfloat162 h0 = split_hi2(c0, c1), h1 = split_hi2(c2, c3);
                __nv_bfloat162 l0 = split_lo2(c0, c1, h0), l1 = split_lo2(c2, c3, h1);
                *(__nv_bfloat162*)&Vh[(long)m0 * N + n0]       = h0;
                *(__nv_bfloat162*)&Vh[(long)(m0 + 8) * N + n0] = h1;
                *(__nv_bfloat162*)&Vl[(long)m0 * N + n0]       = l0;
                *(__nv_bfloat162*)&Vl[(long)(m0 + 8) * N + n0] = l1;
            }
        }
    }
}

// =======================================================================
// Tensor-core flash attention (exact R14 config, best known).
// =======================================================================
#define ATP 72
#define A_QELEMS (64 * ATP)
#define A_STAGE0 (2 * A_QELEMS)
#define A_STAGEE (4 * A_QELEMS)
#define ATTN_SMEM ((A_STAGE0 + 2 * A_STAGEE) * 2)   // 92160 bytes

__global__ __launch_bounds__(128) void attn_tc_kernel(
    const __nv_bfloat16* __restrict__ qh, const __nv_bfloat16* __restrict__ ql,
    const __nv_bfloat16* __restrict__ kh, const __nv_bfloat16* __restrict__ kl,
    const __nv_bfloat16* __restrict__ vh, const __nv_bfloat16* __restrict__ vl,
    const float* __restrict__ mask,
    __nv_bfloat16* __restrict__ avh, __nv_bfloat16* __restrict__ avl)
{
    extern __shared__ __align__(16) __nv_bfloat16 asm_[];
    const unsigned sbase = smem_u32(asm_);

    const int hb = blockIdx.y;
    const int h = hb / BATCH, b = hb % BATCH;
    const int s0 = blockIdx.x * 64;
    const int tid = threadIdx.x;
    const int lane = tid & 31, warp = tid >> 5;

#pragma unroll
    for (int i = 0; i < 8; ++i) {
        int c = tid + i * 128;
        int half = c >> 9, cc = c & 511;
        int row = cc >> 3, kc = cc & 7;
        const __nv_bfloat16* src = (half ? ql : qh) +
            ((long)(s0 + row) * BATCH + b) * DMODEL + h * 64 + kc * 8;
        unsigned d = sbase + (unsigned)((half * A_QELEMS + row * ATP + kc * 8) * 2);
        cp_async16(d, src);
    }
    cp_commit();

    auto issue_kv = [&](int l0, int s) {
        unsigned st = sbase + (unsigned)((A_STAGE0 + s * A_STAGEE) * 2);
#pragma unroll
        for (int i = 0; i < 16; ++i) {
            int c = tid + i * 128;
            int arr = c >> 9, cc = c & 511;
            int row = cc >> 3, kc = cc & 7;
            const __nv_bfloat16* base =
                (arr == 0) ? kh : (arr == 1) ? kl : (arr == 2) ? vh : vl;
            const __nv_bfloat16* src = base +
                ((long)(l0 + row) * BATCH + b) * DMODEL + h * 64 + kc * 8;
            unsigned d = st + (unsigned)((arr * A_QELEMS + row * ATP + kc * 8) * 2);
            cp_async16(d, src);
        }
        cp_commit();
    };

    issue_kv(0, 0);
    cp_wait0();
    __syncthreads();

    unsigned qfh[4][4], qfl[4][4];
    {
        unsigned qb = sbase + (unsigned)(((warp * 16 + (lane & 15)) * ATP + (lane >> 4) * 8) * 2);
        const unsigned qlo = A_QELEMS * 2;
#pragma unroll
        for (int ks = 0; ks < 4; ++ks) {
            ldm_x4(qfh[ks], qb + ks * 32);
            ldm_x4(qfl[ks], qb + ks * 32 + qlo);
        }
    }

    float oacc[8][4];
#pragma unroll
    for (int n = 0; n < 8; ++n)
#pragma unroll
        for (int j = 0; j < 4; ++j) oacc[n][j] = 0.0f;
    float m0 = -1e30f, m1 = -1e30f, ls0 = 0.0f, ls1 = 0.0f;

    const unsigned fragoff = (unsigned)(((lane & 15) * ATP + (lane >> 4) * 8) * 2);
    const unsigned KLD = A_QELEMS * 2;
    const unsigned VOFF = 2 * A_QELEMS * 2;

    const int r0g = s0 + warp * 16 + (lane >> 2);
    const float* mrow0 = mask + (long)r0g * LTOT + (lane & 3) * 2;
    const float* mrow1 = mrow0 + 8L * LTOT;

    const int NIT = LTOT / 64;
    for (int it = 0; it < NIT; ++it) {
        if (it + 1 < NIT) issue_kv((it + 1) * 64, (it + 1) & 1);

        const unsigned stB = sbase + (unsigned)((A_STAGE0 + (it & 1) * A_STAGEE) * 2);
        const unsigned krow = stB + fragoff;
        const unsigned vrow = stB + VOFF + fragoff;
        const int l0 = it * 64;

        float sacc[8][4];
#pragma unroll
        for (int n = 0; n < 8; ++n)
#pragma unroll
            for (int j = 0; j < 4; ++j) sacc[n][j] = 0.0f;

#pragma unroll
        for (int ks = 0; ks < 4; ++ks) {
#pragma unroll
            for (int ng = 0; ng < 4; ++ng) {
                unsigned kbh[4], kbl[4];
                unsigned addr = krow + (unsigned)((ng * 16 * ATP + ks * 16) * 2);
                ldm_x4(kbh, addr);
                ldm_x4(kbl, addr + KLD);
#pragma unroll
                for (int s = 0; s < 2; ++s) {
                    float* d = sacc[ng * 2 + s];
                    mma_bf16(d, qfh[ks], kbh[s], kbh[s + 2]);
                    mma_bf16(d, qfl[ks], kbh[s], kbh[s + 2]);
                    mma_bf16(d, qfh[ks], kbl[s], kbl[s + 2]);
                }
            }
        }

        float mx0 = -1e30f, mx1 = -1e30f;
#pragma unroll
        for (int n = 0; n < 8; ++n) {
            float2 mk0 = *(const float2*)&mrow0[l0 + n * 8];
            float2 mk1 = *(const float2*)&mrow1[l0 + n * 8];
            sacc[n][0] = sacc[n][0] * 0.125f + mk0.x;
            sacc[n][1] = sacc[n][1] * 0.125f + mk0.y;
            sacc[n][2] = sacc[n][2] * 0.125f + mk1.x;
            sacc[n][3] = sacc[n][3] * 0.125f + mk1.y;
            mx0 = fmaxf(mx0, fmaxf(sacc[n][0], sacc[n][1]));
            mx1 = fmaxf(mx1, fmaxf(sacc[n][2], sacc[n][3]));
        }
        mx0 = fmaxf(mx0, __shfl_xor_sync(0xffffffffu, mx0, 1));
        mx0 = fmaxf(mx0, __shfl_xor_sync(0xffffffffu, mx0, 2));
        mx1 = fmaxf(mx1, __shfl_xor_sync(0xffffffffu, mx1, 1));
        mx1 = fmaxf(mx1, __shfl_xor_sync(0xffffffffu, mx1, 2));
        float m0n = fmaxf(m0, mx0), m1n = fmaxf(m1, mx1);
        float c0 = __expf(m0 - m0n), c1 = __expf(m1 - m1n);
        m0 = m0n; m1 = m1n;

        float ps0 = 0.0f, ps1 = 0.0f;
#pragma unroll
        for (int n = 0; n < 8; ++n) {
            sacc[n][0] = __expf(sacc[n][0] - m0n);
            sacc[n][1] = __expf(sacc[n][1] - m0n);
            sacc[n][2] = __expf(sacc[n][2] - m1n);
            sacc[n][3] = __expf(sacc[n][3] - m1n);
            ps0 += sacc[n][0] + sacc[n][1];
            ps1 += sacc[n][2] + sacc[n][3];
        }
        ps0 += __shfl_xor_sync(0xffffffffu, ps0, 1);
        ps0 += __shfl_xor_sync(0xffffffffu, ps0, 2);
        ps1 += __shfl_xor_sync(0xffffffffu, ps1, 1);
        ps1 += __shfl_xor_sync(0xffffffffu, ps1, 2);
        ls0 = ls0 * c0 + ps0;
        ls1 = ls1 * c1 + ps1;

#pragma unroll
        for (int n = 0; n < 8; ++n) {
            oacc[n][0] *= c0; oacc[n][1] *= c0;
            oacc[n][2] *= c1; oacc[n][3] *= c1;
        }

        unsigned pah[4][4], pal[4][4];
#pragma unroll
        for (int kp = 0; kp < 4; ++kp) {
            const float* t0 = sacc[2 * kp];
            const float* t1 = sacc[2 * kp + 1];
            pah[kp][0] = pack_hi2(t0[0], t0[1]);
            pah[kp][1] = pack_hi2(t0[2], t0[3]);
            pah[kp][2] = pack_hi2(t1[0], t1[1]);
            pah[kp][3] = pack_hi2(t1[2], t1[3]);
            pal[kp][0] = pack_lo2(t0[0], t0[1], pah[kp][0]);
            pal[kp][1] = pack_lo2(t0[2], t0[3], pah[kp][1]);
            pal[kp][2] = pack_lo2(t1[0], t1[1], pah[kp][2]);
            pal[kp][3] = pack_lo2(t1[2], t1[3], pah[kp][3]);
        }

#pragma unroll
        for (int kp = 0; kp < 4; ++kp) {
#pragma unroll
            for (int ng = 0; ng < 4; ++ng) {
                unsigned vbh[4], vbl[4];
                unsigned addr = vrow + (unsigned)((kp * 16 * ATP + ng * 16) * 2);
                ldm_x4_t(vbh, addr);
                ldm_x4_t(vbl, addr + KLD);
#pragma unroll
                for (int s = 0; s < 2; ++s) {
                    float* d = oacc[ng * 2 + s];
                    mma_bf16(d, pah[kp], vbh[s * 2], vbh[s * 2 + 1]);
                    mma_bf16(d, pal[kp], vbh[s * 2], vbh[s * 2 + 1]);
                    mma_bf16(d, pah[kp], vbl[s * 2], vbl[s * 2 + 1]);
                }
            }
        }

        if (it + 1 < NIT) {
            cp_wait0();
            __syncthreads();
        }
    }

    float inv0 = 1.0f / ls0, inv1 = 1.0f / ls1;
#pragma unroll
    for (int n = 0; n < 8; ++n) {
        int col = h * 64 + n * 8 + (lane & 3) * 2;
        long i0 = ((long)r0g * BATCH + b) * DMODEL + col;
        long i1 = ((long)(r0g + 8) * BATCH + b) * DMODEL + col;
        float a0 = oacc[n][0] * inv0, a1 = oacc[n][1] * inv0;
        float a2 = oacc[n][2] * inv1, a3 = oacc[n][3] * inv1;
        __nv_bfloat162 h0 = split_hi2(a0, a1), h1 = split_hi2(a2, a3);
        __nv_bfloat162 l0 = split_lo2(a0, a1, h0), l1 = split_lo2(a2, a3, h1);
        *(__nv_bfloat162*)&avh[i0] = h0;
        *(__nv_bfloat162*)&avh[i1] = h1;
        *(__nv_bfloat162*)&avl[i0] = l0;
        *(__nv_bfloat162*)&avl[i1] = l1;
    }
}

// ---------------- LayerNorm over D=1024 (+ optional hi/lo bf16 out) ----
__global__ __launch_bounds__(256) void ln_kernel(
    const float* __restrict__ in, float* __restrict__ out,
    const float* __restrict__ g, const float* __restrict__ bta,
    __nv_bfloat16* __restrict__ oh, __nv_bfloat16* __restrict__ ol)
{
    const int row = blockIdx.x;
    const float* x = in + (long)row * DMODEL;
    const int tid = threadIdx.x;
    float v[4];
    float s = 0.0f, s2 = 0.0f;
#pragma unroll
    for (int i = 0; i < 4; ++i) {
        v[i] = x[tid + i * 256];
        s += v[i];
        s2 += v[i] * v[i];
    }
    __shared__ float rs[8], rs2[8];
#pragma unroll
    for (int o = 16; o > 0; o >>= 1) {
        s  += __shfl_xor_sync(0xffffffffu, s, o);
        s2 += __shfl_xor_sync(0xffffffffu, s2, o);
    }
    if ((tid & 31) == 0) { rs[tid >> 5] = s; rs2[tid >> 5] = s2; }
    __syncthreads();
    if (tid < 32) {
        s  = (tid < 8) ? rs[tid]  : 0.0f;
        s2 = (tid < 8) ? rs2[tid] : 0.0f;
#pragma unroll
        for (int o = 4; o > 0; o >>= 1) {
            s  += __shfl_xor_sync(0xffffffffu, s, o);
            s2 += __shfl_xor_sync(0xffffffffu, s2, o);
        }
        if (tid == 0) { rs[0] = s; rs2[0] = s2; }
    }
    __syncthreads();
    float mu  = rs[0] * (1.0f / DMODEL);
    float var = rs2[0] * (1.0f / DMODEL) - mu * mu;
    float inv = rsqrtf(var + 1e-5f);
#pragma unroll
    for (int i = 0; i < 4; ++i) {
        int c = tid + i * 256;
        float y = (v[i] - mu) * inv * g[c] + bta[c];
        out[(long)row * DMODEL + c] = y;
        if (oh) {
            __nv_bfloat16 hb = __float2bfloat16_rn(y);
            oh[(long)row * DMODEL + c] = hb;
            ol[(long)row * DMODEL + c] =
                __float2bfloat16_rn(y - __bfloat162float(hb));
        }
    }
}

// ---------------- launch ----------------
extern "C" void kernel_launch(void* const* d_in, const int* in_sizes, int n_in,
                              void* d_out, int out_size)
{
    const float* x      = (const float*)d_in[0];
    const float* mask   = (const float*)d_in[1];
    const float* memory = (const float*)d_in[2];

    int o = 3;
    if (n_in >= 16 && in_sizes[3] == 1) o = 4;
    const float* wq   = (const float*)d_in[o + 0];
    const float* wk   = (const float*)d_in[o + 1];
    const float* wv   = (const float*)d_in[o + 2];
    const float* wc   = (const float*)d_in[o + 3];
    const float* w1   = (const float*)d_in[o + 4];
    const float* b1   = (const float*)d_in[o + 5];
    const float* w2   = (const float*)d_in[o + 6];
    const float* b2   = (const float*)d_in[o + 7];
    const float* ln1g = (const float*)d_in[o + 8];
    const float* ln1b = (const float*)d_in[o + 9];
    const float* ln2g = (const float*)d_in[o + 10];
    const float* ln2b = (const float*)d_in[o + 11];
    float* out = (float*)d_out;

    float *upre, *u;
    __nv_bfloat16 *wh, *wl, *xmh, *xml, *qh, *ql, *kh, *kl, *vh, *vl;
    __nv_bfloat16 *avh, *avl, *uh, *ul, *ffh, *ffl;
    cudaGetSymbolAddress((void**)&upre, g_upre);
    cudaGetSymbolAddress((void**)&u,    g_u);
    cudaGetSymbolAddress((void**)&wh,   g_wh);
    cudaGetSymbolAddress((void**)&wl,   g_wl);
    cudaGetSymbolAddress((void**)&xmh,  g_xmh);
    cudaGetSymbolAddress((void**)&xml,  g_xml);
    cudaGetSymbolAddress((void**)&qh,   g_qh);
    cudaGetSymbolAddress((void**)&ql,   g_ql);
    cudaGetSymbolAddress((void**)&kh,   g_kh);
    cudaGetSymbolAddress((void**)&kl,   g_kl);
    cudaGetSymbolAddress((void**)&vh,   g_vh);
    cudaGetSymbolAddress((void**)&vl,   g_vl);
    cudaGetSymbolAddress((void**)&avh,  g_avh);
    cudaGetSymbolAddress((void**)&avl,  g_avl);
    cudaGetSymbolAddress((void**)&uh,   g_uh);
    cudaGetSymbolAddress((void**)&ul,   g_ul);
    cudaGetSymbolAddress((void**)&ffh,  g_ffh);
    cudaGetSymbolAddress((void**)&ffl,  g_ffl);

    cudaFuncSetAttribute(gemm_bf_kernel,
                         cudaFuncAttributeMaxDynamicSharedMemorySize, G_SMEM);
    cudaFuncSetAttribute(gemm_kv_kernel,
                         cudaFuncAttributeMaxDynamicSharedMemorySize, F_SMEM);
    cudaFuncSetAttribute(attn_tc_kernel,
                         cudaFuncAttributeMaxDynamicSharedMemorySize, ATTN_SMEM);

    dim3 thr(256);
    const long XOFF = (long)MEMLEN * NROWS * DMODEL;

    // ---- ONE fused convert launch for all 8 regions ----
    fused_split_kernel<<<SC8 / 256, 256>>>(
        wq, wk, wv, wc, w1, w2, memory, x, wh, wl, xmh, xml);

    // ---- Q GEMM (bf16 out) ----
    gemm_bf_kernel<<<dim3(DMODEL / BN, NROWS / BM), thr, G_SMEM>>>(
        xmh + XOFF, xml + XOFF, wh + WQ_OFF, wl + WQ_OFF,
        nullptr, nullptr, nullptr, qh, ql, DMODEL, DMODEL, 0);
    // ---- fused K+V GEMM: A loaded once ----
    gemm_kv_kernel<<<dim3(DMODEL / BN, KVROWS / BM), 128, F_SMEM>>>(
        xmh, xml, wh + WK_OFF, wl + WK_OFF, wh + WV_OFF, wl + WV_OFF,
        kh, kl, vh, vl, DMODEL, DMODEL);

    // ---- attention ----
    attn_tc_kernel<<<dim3(SEQ / 64, HEADS * BATCH), 128, ATTN_SMEM>>>(
        qh, ql, kh, kl, vh, vl, mask, avh, avl);

    // ---- u_pre = av @ wc^T + x (fp32), LN1 -> u (fp32 + bf16) ----
    gemm_bf_kernel<<<dim3(DMODEL / BN, NROWS / BM), thr, G_SMEM>>>(
        avh, avl, wh + WC_OFF, wl + WC_OFF,
        nullptr, x, upre, nullptr, nullptr, DMODEL, DMODEL, 0);
    ln_kernel<<<NROWS, 256>>>(upre, u, ln1g, ln1b, uh, ul);

    // ---- ff = relu(u @ w1^T + b1) (bf16 out) ----
    gemm_bf_kernel<<<dim3(MFF / BN, NROWS / BM), thr, G_SMEM>>>(
        uh, ul, wh + W1_OFF, wl + W1_OFF,
        b1, nullptr, nullptr, ffh, ffl, MFF, DMODEL, 1);

    // ---- z_pre = ff @ w2^T + b2 + u (fp32), LN2 in-place ----
    gemm_bf_kernel<<<dim3(DMODEL / BN, NROWS / BM), thr, G_SMEM>>>(
        ffh, ffl, wh + W2_OFF, wl + W2_OFF,
        b2, u, out, nullptr, nullptr, DMODEL, MFF, 0);
    ln_kernel<<<NROWS, 256>>>(out, out, ln2g, ln2b, nullptr, nullptr);
}